// round 5
// baseline (speedup 1.0000x reference)
#include <cuda_runtime.h>

// Problem constants (fixed by setup_inputs)
#define M_PTS   1024
#define BATCH   2
#define NC      64
#define KS      13
#define NA      20
#define DOUT    64
#define KP      (KS * NA)          // 260 kernel positions
#define R2      0.16f              // RADIUS^2
// S = -log2(e) / (2*SIGMA) = -1.4426950408889634 / 0.16
#define S_CONST (-9.016844005556021f)
#define M2S     (18.033688011112042f)   // -2*S

#define NTHREADS 320
#define NWARPS   (NTHREADS / 32)

__device__ __forceinline__ float ex2(float x) {
    float y;
    asm("ex2.approx.ftz.f32 %0, %1;" : "=f"(y) : "f"(x));
    return y;
}

__global__ __launch_bounds__(NTHREADS, 1)
void kp_fused_kernel(const float* __restrict__ frag,      // (M,3)
                     const float* __restrict__ clouds,    // (B,3,NC)
                     const float* __restrict__ kernels,   // (KS,NA,3) -> contiguous [KP][3]
                     const float* __restrict__ W,         // (DOUT,KS)
                     float* __restrict__ out)             // (B,DOUT,NC,NA)
{
    __shared__ float4 s_pts[M_PTS];      // gathered relative coords + |r|^2*S
    __shared__ float  s_wts[KP];
    __shared__ float  s_W[DOUT * KS];
    __shared__ int    s_wcnt[2][NWARPS];

    const int tid  = threadIdx.x;
    const int lane = tid & 31;
    const int wrp  = tid >> 5;

    const int bidx = blockIdx.x;         // b*NC + n
    const int bb   = bidx / NC;
    const int n    = bidx % NC;

    const float cx = clouds[bb * 3 * NC + 0 * NC + n];
    const float cy = clouds[bb * 3 * NC + 1 * NC + n];
    const float cz = clouds[bb * 3 * NC + 2 * NC + n];

    // Preload conv weights into shared (tiny, overlaps with phase 1)
    for (int i = tid; i < DOUT * KS; i += NTHREADS) s_W[i] = W[i];

    // ---------------- Phase 1: deterministic in-ball compaction ----------------
    int base = 0;
    #pragma unroll
    for (int chunk = 0; chunk < (M_PTS + NTHREADS - 1) / NTHREADS; chunk++) {
        const int i = chunk * NTHREADS + tid;
        bool pred = false;
        float rx = 0.f, ry = 0.f, rz = 0.f, rn2 = 0.f;
        if (i < M_PTS) {
            rx = frag[3 * i + 0] - cx;
            ry = frag[3 * i + 1] - cy;
            rz = frag[3 * i + 2] - cz;
            rn2 = fmaf(rz, rz, fmaf(ry, ry, rx * rx));
            pred = rn2 < R2;
        }
        const unsigned bal = __ballot_sync(0xffffffffu, pred);
        const int buf = chunk & 1;
        if (lane == 0) s_wcnt[buf][wrp] = __popc(bal);
        __syncthreads();
        int prefix = 0, total = 0;
        #pragma unroll
        for (int w = 0; w < NWARPS; w++) {
            const int c = s_wcnt[buf][w];
            if (w < wrp) prefix += c;
            total += c;
        }
        if (pred) {
            const int pos = base + prefix + __popc(bal & ((1u << lane) - 1u));
            s_pts[pos] = make_float4(rx, ry, rz, rn2 * S_CONST);
        }
        base += total;   // every thread tracks the running total identically
    }
    __syncthreads();
    const int cnt = base;   // == nnctn for this center

    // ---------------- Phase 2: per-kernel-position gaussian accumulation -------
    if (tid < KP) {
        const float kx = kernels[3 * tid + 0];
        const float ky = kernels[3 * tid + 1];
        const float kz = kernels[3 * tid + 2];
        const float ps = fmaf(kz, kz, fmaf(ky, ky, kx * kx)) * S_CONST;

        float a0 = 0.f, a1 = 0.f, a2 = 0.f, a3 = 0.f;
        int i = 0;
        for (; i + 4 <= cnt; i += 4) {
            const float4 r0 = s_pts[i + 0];
            const float4 r1 = s_pts[i + 1];
            const float4 r2 = s_pts[i + 2];
            const float4 r3 = s_pts[i + 3];
            const float d0 = fmaf(r0.z, kz, fmaf(r0.y, ky, r0.x * kx));
            const float d1 = fmaf(r1.z, kz, fmaf(r1.y, ky, r1.x * kx));
            const float d2 = fmaf(r2.z, kz, fmaf(r2.y, ky, r2.x * kx));
            const float d3 = fmaf(r3.z, kz, fmaf(r3.y, ky, r3.x * kx));
            a0 += ex2(fmaf(d0, M2S, r0.w + ps));
            a1 += ex2(fmaf(d1, M2S, r1.w + ps));
            a2 += ex2(fmaf(d2, M2S, r2.w + ps));
            a3 += ex2(fmaf(d3, M2S, r3.w + ps));
        }
        for (; i < cnt; i++) {
            const float4 r0 = s_pts[i];
            const float d0 = fmaf(r0.z, kz, fmaf(r0.y, ky, r0.x * kx));
            a0 += ex2(fmaf(d0, M2S, r0.w + ps));
        }
        s_wts[tid] = ((a0 + a1) + (a2 + a3)) / ((float)cnt + 1.0f);
    }
    __syncthreads();

    // ---------------- Phase 3: 1x1 SO3 conv + store ----------------------------
    // feats[b,o,n,a] = sum_k W[o,k] * wts[k,n,a]
    for (int oa = tid; oa < DOUT * NA; oa += NTHREADS) {
        const int o = oa / NA;
        const int a = oa % NA;
        float s = 0.f;
        #pragma unroll
        for (int k = 0; k < KS; k++)
            s = fmaf(s_W[o * KS + k], s_wts[k * NA + a], s);
        out[(bb * DOUT + o) * (NC * NA) + n * NA + a] = s;
    }
}

extern "C" void kernel_launch(void* const* d_in, const int* in_sizes, int n_in,
                              void* d_out, int out_size) {
    const float* frag    = (const float*)d_in[0];   // (1024,3)
    const float* clouds  = (const float*)d_in[1];   // (2,3,64)
    const float* kernels = (const float*)d_in[2];   // (13,20,3)
    const float* W       = (const float*)d_in[3];   // (64,13)
    float* out = (float*)d_out;                     // (2,64,64,20)

    kp_fused_kernel<<<BATCH * NC, NTHREADS>>>(frag, clouds, kernels, W, out);
}

// round 6
// speedup vs baseline: 1.6000x; 1.6000x over previous
#include <cuda_runtime.h>

// Problem constants (fixed by setup_inputs)
#define M_PTS   1024
#define BATCH   2
#define NC      64
#define KS      13
#define NA      20
#define DOUT    64
#define KP      (KS * NA)          // 260 kernel positions
#define R2      0.16f              // RADIUS^2
// S = -log2(e) / (2*SIGMA) = -1.4426950408889634 / 0.16
#define S_CONST (-9.016844005556021f)
#define M2S     (18.033688011112042f)   // -2*S

#define NTHREADS 640
#define NWARPS   (NTHREADS / 32)
#define NCHUNKS  ((M_PTS + NTHREADS - 1) / NTHREADS)   // 2

__device__ __forceinline__ float ex2(float x) {
    float y;
    asm("ex2.approx.ftz.f32 %0, %1;" : "=f"(y) : "f"(x));
    return y;
}

__global__ __launch_bounds__(NTHREADS, 1)
void kp_fused_kernel(const float* __restrict__ frag,      // (M,3)
                     const float* __restrict__ clouds,    // (B,3,NC)
                     const float* __restrict__ kernels,   // (KS,NA,3) -> [KP][3]
                     const float* __restrict__ W,         // (DOUT,KS)
                     float* __restrict__ out)             // (B,DOUT,NC,NA)
{
    __shared__ float4 s_pts[M_PTS];      // compacted relative coords + |r|^2*S
    __shared__ float  s_wts[KP];
    __shared__ float  s_W[DOUT * KS];
    __shared__ int    s_wcnt[NCHUNKS][NWARPS];

    const int tid  = threadIdx.x;
    const int lane = tid & 31;
    const int wrp  = tid >> 5;

    const int bidx = blockIdx.x;         // b*NC + n
    const int bb   = bidx >> 6;          // / NC
    const int n    = bidx & 63;          // % NC

    // Issue kernel-position loads early (L2-resident after first wave);
    // 2 threads per kernel position, padded threads duplicate kp 0.
    const int  par   = tid & 1;
    int        kp    = tid >> 1;
    const bool valid = (kp < KP);
    if (!valid) kp = 0;
    const float kx = kernels[3 * kp + 0];
    const float ky = kernels[3 * kp + 1];
    const float kz = kernels[3 * kp + 2];

    const float cx = clouds[bb * 3 * NC + 0 * NC + n];
    const float cy = clouds[bb * 3 * NC + 1 * NC + n];
    const float cz = clouds[bb * 3 * NC + 2 * NC + n];

    // Preload conv weights into shared (tiny, overlaps phase 1)
    for (int i = tid; i < DOUT * KS; i += NTHREADS) s_W[i] = W[i];

    // ---------------- Phase 1: deterministic in-ball compaction ----------------
    int base = 0;
    #pragma unroll
    for (int chunk = 0; chunk < NCHUNKS; chunk++) {
        const int i = chunk * NTHREADS + tid;
        bool pred = false;
        float rx = 0.f, ry = 0.f, rz = 0.f, rn2 = 0.f;
        if (i < M_PTS) {
            rx = frag[3 * i + 0] - cx;
            ry = frag[3 * i + 1] - cy;
            rz = frag[3 * i + 2] - cz;
            rn2 = fmaf(rz, rz, fmaf(ry, ry, rx * rx));
            pred = rn2 < R2;
        }
        const unsigned bal = __ballot_sync(0xffffffffu, pred);
        if (lane == 0) s_wcnt[chunk][wrp] = __popc(bal);
        __syncthreads();
        int prefix = 0, total = 0;
        #pragma unroll
        for (int w = 0; w < NWARPS; w++) {
            const int c = s_wcnt[chunk][w];
            if (w < wrp) prefix += c;
            total += c;
        }
        if (pred) {
            const int pos = base + prefix + __popc(bal & ((1u << lane) - 1u));
            s_pts[pos] = make_float4(rx, ry, rz, rn2 * S_CONST);
        }
        base += total;   // identical running total in every thread
    }
    const int cnt = base;   // == nnctn for this center
    __syncthreads();

    // ------- Phase 2: gaussian accumulation, 2 threads per kernel position -----
    {
        const float ps = fmaf(kz, kz, fmaf(ky, ky, kx * kx)) * S_CONST;

        float a0 = 0.f, a1 = 0.f, a2 = 0.f, a3 = 0.f;
        int i = par;
        for (; i + 6 < cnt; i += 8) {
            const float4 r0 = s_pts[i + 0];
            const float4 r1 = s_pts[i + 2];
            const float4 r2 = s_pts[i + 4];
            const float4 r3 = s_pts[i + 6];
            const float d0 = fmaf(r0.z, kz, fmaf(r0.y, ky, r0.x * kx));
            const float d1 = fmaf(r1.z, kz, fmaf(r1.y, ky, r1.x * kx));
            const float d2 = fmaf(r2.z, kz, fmaf(r2.y, ky, r2.x * kx));
            const float d3 = fmaf(r3.z, kz, fmaf(r3.y, ky, r3.x * kx));
            a0 += ex2(fmaf(d0, M2S, r0.w + ps));
            a1 += ex2(fmaf(d1, M2S, r1.w + ps));
            a2 += ex2(fmaf(d2, M2S, r2.w + ps));
            a3 += ex2(fmaf(d3, M2S, r3.w + ps));
        }
        for (; i < cnt; i += 2) {
            const float4 r0 = s_pts[i];
            const float d0 = fmaf(r0.z, kz, fmaf(r0.y, ky, r0.x * kx));
            a0 += ex2(fmaf(d0, M2S, r0.w + ps));
        }
        float sum = (a0 + a1) + (a2 + a3);
        // combine even/odd partner lanes (pairs are lane-adjacent; full warp active)
        sum += __shfl_xor_sync(0xffffffffu, sum, 1);
        if (valid && par == 0)
            s_wts[kp] = __fdividef(sum, (float)cnt + 1.0f);
    }
    __syncthreads();

    // ---------------- Phase 3: 1x1 SO3 conv + store ----------------------------
    // feats[b,o,n,a] = sum_k W[o,k] * wts[k,n,a]
    #pragma unroll
    for (int oa = tid; oa < DOUT * NA; oa += NTHREADS) {
        const int o = oa / NA;
        const int a = oa % NA;
        float s = 0.f;
        #pragma unroll
        for (int k = 0; k < KS; k++)
            s = fmaf(s_W[o * KS + k], s_wts[k * NA + a], s);
        out[(bb * DOUT + o) * (NC * NA) + n * NA + a] = s;
    }
}

extern "C" void kernel_launch(void* const* d_in, const int* in_sizes, int n_in,
                              void* d_out, int out_size) {
    const float* frag    = (const float*)d_in[0];   // (1024,3)
    const float* clouds  = (const float*)d_in[1];   // (2,3,64)
    const float* kernels = (const float*)d_in[2];   // (13,20,3)
    const float* W       = (const float*)d_in[3];   // (64,13)
    float* out = (float*)d_out;                     // (2,64,64,20)

    kp_fused_kernel<<<BATCH * NC, NTHREADS>>>(frag, clouds, kernels, W, out);
}